// round 7
// baseline (speedup 1.0000x reference)
#include <cuda_runtime.h>
#include <math.h>
#include <stdint.h>

#define B_  8
#define NW_ 64
#define P_  160
#define E_  512
#define H_  8
#define D_  64
#define M_  (B_*NW_*P_)               // 81920
#define QKV_ELEMS (B_*H_*NW_*P_*D_)   // 41,943,040

// Scratch
__device__ float g_q[QKV_ELEMS];
__device__ float g_k[QKV_ELEMS];
__device__ float g_v[QKV_ELEMS];
__device__ float g_x[M_*E_];          // rna-rounded patches
__device__ float g_w[3][E_*E_];       // rna-rounded weights

__device__ __forceinline__ uint32_t smem_u32(const void* p) {
    uint32_t a;
    asm("{ .reg .u64 t; cvta.to.shared.u64 t, %1; cvt.u32.u64 %0, t; }" : "=r"(a) : "l"(p));
    return a;
}
__device__ __forceinline__ float rna_tf32(float f) {
    uint32_t r;
    asm("cvt.rna.tf32.f32 %0, %1;" : "=r"(r) : "f"(f));
    return __uint_as_float(r);
}

#define CP_ASYNC16(dst, src) \
    asm volatile("cp.async.cg.shared.global [%0], [%1], 16;" :: "r"(dst), "l"(src))
#define CP_COMMIT()  asm volatile("cp.async.commit_group;" ::: "memory")
#define CP_WAIT(n)   asm volatile("cp.async.wait_group %0;" :: "n"(n) : "memory")

__device__ __forceinline__ void mma_tf32(float* c, const uint32_t* a, const uint32_t* b) {
    asm volatile(
        "mma.sync.aligned.m16n8k8.row.col.f32.tf32.tf32.f32 "
        "{%0,%1,%2,%3}, {%4,%5,%6,%7}, {%8,%9}, {%0,%1,%2,%3};"
        : "+f"(c[0]), "+f"(c[1]), "+f"(c[2]), "+f"(c[3])
        : "r"(a[0]), "r"(a[1]), "r"(a[2]), "r"(a[3]), "r"(b[0]), "r"(b[1]));
}

// ---------------------------------------------------------------------------
// Prepass: rna-round patches and weights to tf32 precision.
// ---------------------------------------------------------------------------
#define XN4 (M_*E_/4)                  // 10,485,760
#define WN4 (E_*E_/4)                  // 65,536
#define TOT4 (XN4 + 3*WN4)

__global__ __launch_bounds__(256) void prepass(
    const float* __restrict__ x,
    const float* __restrict__ wq, const float* __restrict__ wk,
    const float* __restrict__ wv)
{
    int gid = blockIdx.x * 256 + threadIdx.x;
    if (gid >= TOT4) return;
    const float* src;
    float* dst;
    if (gid < XN4) { src = x; dst = g_x; }
    else {
        int j = gid - XN4;
        int which = j / WN4;
        gid = j - which * WN4;
        src = (which == 0) ? wq : (which == 1) ? wk : wv;
        dst = g_w[which];
    }
    float4 v = *(const float4*)(src + (size_t)gid * 4);
    v.x = rna_tf32(v.x); v.y = rna_tf32(v.y);
    v.z = rna_tf32(v.z); v.w = rna_tf32(v.w);
    *(float4*)(dst + (size_t)gid * 4) = v;
}

// ---------------------------------------------------------------------------
// QKV projection via tf32 mma.sync.
// CTA: 128(M) x 256(N), 8 warps in 2x4, warp tile 64x64 (4x8 m16n8k8 tiles).
// BK=16 double-buffered cp.async; smem stride 20 (conflict-free frag loads).
// ---------------------------------------------------------------------------
#define STRIDE_ 20
#define QKV_SMEM_BYTES ((2*128*STRIDE_ + 2*256*STRIDE_) * 4)   // 61440

__global__ __launch_bounds__(256, 1) void qkv_mma(
    const float* __restrict__ bq, const float* __restrict__ bk,
    const float* __restrict__ bv)
{
    extern __shared__ float dsm[];
    float* Asm = dsm;                 // [2][128][20]
    float* Bsm = dsm + 2 * 128 * STRIDE_;  // [2][256][20]

    const float* wgt; const float* bias; float* outp;
    if (blockIdx.z == 0)      { wgt = g_w[0]; bias = bq; outp = g_q; }
    else if (blockIdx.z == 1) { wgt = g_w[1]; bias = bk; outp = g_k; }
    else                      { wgt = g_w[2]; bias = bv; outp = g_v; }

    const int m0 = blockIdx.x * 128;
    const int f0 = blockIdx.y * 256;
    const int tid = threadIdx.x;
    const int wid = tid >> 5;
    const int lane = tid & 31;
    const int g = lane >> 2;
    const int t = lane & 3;

    const int warp_m = (wid & 1) * 64;
    const int warp_n = (wid >> 1) * 64;

    const int r0 = tid >> 2;          // 0..63
    const int s0 = (tid & 3) * 4;     // k-seg

    float c[4][8][4];
#pragma unroll
    for (int i = 0; i < 4; i++)
#pragma unroll
        for (int j = 0; j < 8; j++)
#pragma unroll
            for (int k = 0; k < 4; k++) c[i][j][k] = 0.0f;

    const float* xa = g_x + (size_t)m0 * E_;
    const float* wa = wgt + (size_t)f0 * E_;

    // Stage macro: A rows r0, r0+64; B rows r0, +64, +128, +192
#define STAGE(bufsel, koff)                                                        \
    {                                                                              \
        float* ab = Asm + (bufsel) * 128 * STRIDE_;                                \
        float* bb = Bsm + (bufsel) * 256 * STRIDE_;                                \
        CP_ASYNC16(smem_u32(ab + (r0) * STRIDE_ + s0),                             \
                   xa + (size_t)(r0) * E_ + (koff) + s0);                          \
        CP_ASYNC16(smem_u32(ab + (r0 + 64) * STRIDE_ + s0),                        \
                   xa + (size_t)(r0 + 64) * E_ + (koff) + s0);                     \
        CP_ASYNC16(smem_u32(bb + (r0) * STRIDE_ + s0),                             \
                   wa + (size_t)(r0) * E_ + (koff) + s0);                          \
        CP_ASYNC16(smem_u32(bb + (r0 + 64) * STRIDE_ + s0),                        \
                   wa + (size_t)(r0 + 64) * E_ + (koff) + s0);                     \
        CP_ASYNC16(smem_u32(bb + (r0 + 128) * STRIDE_ + s0),                       \
                   wa + (size_t)(r0 + 128) * E_ + (koff) + s0);                    \
        CP_ASYNC16(smem_u32(bb + (r0 + 192) * STRIDE_ + s0),                       \
                   wa + (size_t)(r0 + 192) * E_ + (koff) + s0);                    \
        CP_COMMIT();                                                               \
    }

    STAGE(0, 0)

    int buf = 0;
    for (int kt = 0; kt < E_; kt += 16) {
        if (kt + 16 < E_) {
            STAGE(buf ^ 1, kt + 16)
            CP_WAIT(1);
        } else {
            CP_WAIT(0);
        }
        __syncthreads();

        const float* ab = Asm + buf * 128 * STRIDE_;
        const float* bb = Bsm + buf * 256 * STRIDE_;
#pragma unroll
        for (int kk = 0; kk < 16; kk += 8) {
            uint32_t a[4][4], bfr[8][2];
#pragma unroll
            for (int tm = 0; tm < 4; tm++) {
                const float* base = ab + (warp_m + tm * 16 + g) * STRIDE_ + kk + t;
                a[tm][0] = *(const uint32_t*)(base);
                a[tm][1] = *(const uint32_t*)(base + 8 * STRIDE_);
                a[tm][2] = *(const uint32_t*)(base + 4);
                a[tm][3] = *(const uint32_t*)(base + 8 * STRIDE_ + 4);
            }
#pragma unroll
            for (int tn = 0; tn < 8; tn++) {
                const float* base = bb + (warp_n + tn * 8 + g) * STRIDE_ + kk + t;
                bfr[tn][0] = *(const uint32_t*)(base);
                bfr[tn][1] = *(const uint32_t*)(base + 4);
            }
#pragma unroll
            for (int tm = 0; tm < 4; tm++)
#pragma unroll
                for (int tn = 0; tn < 8; tn++)
                    mma_tf32(c[tm][tn], a[tm], bfr[tn]);
        }
        __syncthreads();
        buf ^= 1;
    }
#undef STAGE

    // Epilogue: bias + scatter into [B,H,NW,P,D]
#pragma unroll
    for (int tm = 0; tm < 4; tm++) {
        const int mr0 = m0 + warp_m + tm * 16 + g;
#pragma unroll
        for (int rr = 0; rr < 2; rr++) {
            const int m = mr0 + rr * 8;
            const int bi  = m / (NW_ * P_);
            const int rem = m - bi * (NW_ * P_);
            const int ww  = rem / P_;
            const int p   = rem - ww * P_;
            const size_t rowbase = ((size_t)(bi * H_) * NW_ + ww) * P_ + p;
#pragma unroll
            for (int tn = 0; tn < 8; tn++) {
                const int col = f0 + warp_n + tn * 8 + t * 2;
                const int hh = col >> 6;
                const int d0 = col & 63;
                float2 o;
                o.x = c[tm][tn][rr * 2 + 0] + bias[col];
                o.y = c[tm][tn][rr * 2 + 1] + bias[col + 1];
                *(float2*)(outp + (rowbase + (size_t)hh * NW_ * P_) * D_ + d0) = o;
            }
        }
    }
}

// ---------------------------------------------------------------------------
// Attention on mma.sync tf32 (unchanged from R6). One CTA (512 thr) per (b,h,w).
// ---------------------------------------------------------------------------
#define QS_STR 68
#define KS_STR 68
#define SS_STR 196
#define VT_STR 196
#define OFF_KS 10880
#define OFF_SS (10880 + 13056)
#define ATT_SMEM_BYTES ((OFF_SS + 160 * SS_STR) * 4)   // 221184

__global__ __launch_bounds__(512) void attn_mma(
    const float* __restrict__ pos_bias,
    float* __restrict__ out)
{
    extern __shared__ float smf[];
    float* Qs = smf;
    float* Ks = smf + OFF_KS;     // doubles as Vt later
    float* Ss = smf + OFF_SS;
    __shared__ float pb[19 * 31];
    __shared__ float rsum[160];

    const int w = blockIdx.x, h = blockIdx.y, b = blockIdx.z;
    const int tid = threadIdx.x;
    const int lane = tid & 31, warp = tid >> 5;
    const int g = lane >> 2, t = lane & 3;
    const float NEG_INF = __int_as_float(0xff800000);

    for (int i = tid; i < 19 * 31; i += 512) pb[i] = pos_bias[i];

    const size_t base = ((size_t)(b * H_ + h) * NW_ + w) * (P_ * D_);
    const float* qg = g_q + base;
    const float* kg = g_k + base;
    const float* vg = g_v + base;

    for (int i = tid; i < P_ * D_ / 4; i += 512) {
        int e = i * 4;
        int p = e >> 6;
        int d = e & 63;
        float4 q4 = *(const float4*)(qg + e);
        q4.x = rna_tf32(q4.x * 0.125f); q4.y = rna_tf32(q4.y * 0.125f);
        q4.z = rna_tf32(q4.z * 0.125f); q4.w = rna_tf32(q4.w * 0.125f);
        *(float4*)(Qs + p * QS_STR + d) = q4;
        float4 k4 = *(const float4*)(kg + e);
        k4.x = rna_tf32(k4.x); k4.y = rna_tf32(k4.y);
        k4.z = rna_tf32(k4.z); k4.w = rna_tf32(k4.w);
        *(float4*)(Ks + p * KS_STR + d) = k4;
    }
    for (int i = tid; i < 32 * KS_STR; i += 512) Ks[160 * KS_STR + i] = 0.0f;
    __syncthreads();

    const int wmS = warp & 1, wnS = warp >> 1;
    const int mS = wmS * 80, nS = wnS * 24;
    float c[5][3][4];
#pragma unroll
    for (int i = 0; i < 5; i++)
#pragma unroll
        for (int j = 0; j < 3; j++)
#pragma unroll
            for (int k = 0; k < 4; k++) c[i][j][k] = 0.0f;

#pragma unroll
    for (int kk = 0; kk < 64; kk += 8) {
        uint32_t a[5][4], bf[3][2];
#pragma unroll
        for (int tm = 0; tm < 5; tm++) {
            const float* ap = &Qs[(mS + tm * 16 + g) * QS_STR + kk + t];
            a[tm][0] = *(const uint32_t*)(ap);
            a[tm][1] = *(const uint32_t*)(ap + 8 * QS_STR);
            a[tm][2] = *(const uint32_t*)(ap + 4);
            a[tm][3] = *(const uint32_t*)(ap + 8 * QS_STR + 4);
        }
#pragma unroll
        for (int tn = 0; tn < 3; tn++) {
            const float* bp = &Ks[(nS + tn * 8 + g) * KS_STR + kk + t];
            bf[tn][0] = *(const uint32_t*)(bp);
            bf[tn][1] = *(const uint32_t*)(bp + 4);
        }
#pragma unroll
        for (int tm = 0; tm < 5; tm++)
#pragma unroll
            for (int tn = 0; tn < 3; tn++)
                mma_tf32(c[tm][tn], a[tm], bf[tn]);
    }

    const int wy = w >> 3, wx = w & 7;
#pragma unroll
    for (int tm = 0; tm < 5; tm++) {
#pragma unroll
        for (int rr = 0; rr < 2; rr++) {
            const int i = mS + tm * 16 + g + rr * 8;
            const int vi = i >> 4, hi = i & 15;
#pragma unroll
            for (int tn = 0; tn < 3; tn++) {
#pragma unroll
                for (int e2 = 0; e2 < 2; e2++) {
                    const int j = nS + tn * 8 + t * 2 + e2;
                    float sv;
                    if (j >= P_) sv = NEG_INF;
                    else {
                        const int vj = j >> 4, hj = j & 15;
                        int dv = vj - vi + 19; if (dv >= 19) dv -= 19;
                        int dh = hj - hi + 31; if (dh >= 31) dh -= 31;
                        float s = c[tm][tn][rr * 2 + e2] + pb[dv * 31 + dh];
                        bool msk = ((wy == 7) && ((vi < 5) != (vj < 5))) ||
                                   ((wx == 7) && ((hi < 8) != (hj < 8)));
                        sv = msk ? NEG_INF : s;
                    }
                    Ss[i * SS_STR + j] = sv;
                }
            }
        }
    }
    __syncthreads();

    float* Vt = Ks;
    for (int i = tid; i < P_ * D_ / 4; i += 512) {
        int e = i * 4;
        int p = e >> 6;
        int d = e & 63;
        float4 v4 = *(const float4*)(vg + e);
        Vt[(d + 0) * VT_STR + p] = rna_tf32(v4.x);
        Vt[(d + 1) * VT_STR + p] = rna_tf32(v4.y);
        Vt[(d + 2) * VT_STR + p] = rna_tf32(v4.z);
        Vt[(d + 3) * VT_STR + p] = rna_tf32(v4.w);
    }
    for (int i = tid; i < 64 * 32; i += 512) {
        int d = i >> 5, pp = 160 + (i & 31);
        Vt[d * VT_STR + pp] = 0.0f;
    }

    for (int r = warp; r < P_; r += 16) {
        float vals[6];
        float mx = NEG_INF;
#pragma unroll
        for (int s6 = 0; s6 < 6; s6++) {
            vals[s6] = Ss[r * SS_STR + lane + 32 * s6];
            mx = fmaxf(mx, vals[s6]);
        }
#pragma unroll
        for (int o = 16; o > 0; o >>= 1)
            mx = fmaxf(mx, __shfl_xor_sync(0xffffffffu, mx, o));
        float sum = 0.0f;
#pragma unroll
        for (int s6 = 0; s6 < 6; s6++) {
            float e = __expf(vals[s6] - mx);
            vals[s6] = e;
            sum += e;
        }
#pragma unroll
        for (int o = 16; o > 0; o >>= 1)
            sum += __shfl_xor_sync(0xffffffffu, sum, o);
#pragma unroll
        for (int s6 = 0; s6 < 6; s6++)
            Ss[r * SS_STR + lane + 32 * s6] = rna_tf32(vals[s6]);
        if (lane == 0) rsum[r] = 1.0f / sum;
    }
    __syncthreads();

    const int wmO = warp >> 3, wnO = warp & 7;
    const int mO = wmO * 80, nO = wnO * 8;
    float o[5][4];
#pragma unroll
    for (int i = 0; i < 5; i++)
#pragma unroll
        for (int k = 0; k < 4; k++) o[i][k] = 0.0f;

    for (int ks = 0; ks < 192; ks += 8) {
        uint32_t a[5][4], bf[2];
#pragma unroll
        for (int tm = 0; tm < 5; tm++) {
            const float* ap = &Ss[(mO + tm * 16 + g) * SS_STR + ks + t];
            a[tm][0] = *(const uint32_t*)(ap);
            a[tm][1] = *(const uint32_t*)(ap + 8 * SS_STR);
            a[tm][2] = *(const uint32_t*)(ap + 4);
            a[tm][3] = *(const uint32_t*)(ap + 8 * SS_STR + 4);
        }
        {
            const float* bp = &Vt[(nO + g) * VT_STR + ks + t];
            bf[0] = *(const uint32_t*)(bp);
            bf[1] = *(const uint32_t*)(bp + 4);
        }
#pragma unroll
        for (int tm = 0; tm < 5; tm++)
            mma_tf32(o[tm], a[tm], bf);
    }

#pragma unroll
    for (int tm = 0; tm < 5; tm++) {
#pragma unroll
        for (int rr = 0; rr < 2; rr++) {
            const int p = mO + tm * 16 + g + rr * 8;
            const float inv = rsum[p];
            float2 o2;
            o2.x = o[tm][rr * 2 + 0] * inv;
            o2.y = o[tm][rr * 2 + 1] * inv;
            *(float2*)(out + ((size_t)(b * NW_ + w) * P_ + p) * E_ + h * D_ + nO + t * 2) = o2;
        }
    }
}

// ---------------------------------------------------------------------------
extern "C" void kernel_launch(void* const* d_in, const int* in_sizes, int n_in,
                              void* d_out, int out_size)
{
    const float* patches  = (const float*)d_in[0];
    const float* wq       = (const float*)d_in[1];
    const float* bq       = (const float*)d_in[2];
    const float* wk       = (const float*)d_in[3];
    const float* bk       = (const float*)d_in[4];
    const float* wv       = (const float*)d_in[5];
    const float* bv       = (const float*)d_in[6];
    const float* pos_bias = (const float*)d_in[7];
    float* out            = (float*)d_out;

    prepass<<<(TOT4 + 255) / 256, 256>>>(patches, wq, wk, wv);

    cudaFuncSetAttribute(qkv_mma,
                         cudaFuncAttributeMaxDynamicSharedMemorySize, QKV_SMEM_BYTES);
    dim3 g1(M_ / 128, E_ / 256, 3);   // (640, 2, 3)
    qkv_mma<<<g1, 256, QKV_SMEM_BYTES>>>(bq, bk, bv);

    cudaFuncSetAttribute(attn_mma,
                         cudaFuncAttributeMaxDynamicSharedMemorySize, ATT_SMEM_BYTES);
    dim3 g2(NW_, H_, B_);             // (64, 8, 8)
    attn_mma<<<g2, 512, ATT_SMEM_BYTES>>>(pos_bias, out);
}

// round 8
// speedup vs baseline: 1.4297x; 1.4297x over previous
#include <cuda_runtime.h>
#include <cuda_fp16.h>
#include <math.h>
#include <stdint.h>

#define B_  8
#define NW_ 64
#define P_  160
#define E_  512
#define H_  8
#define D_  64
#define M_  (B_*NW_*P_)               // 81920
#define QKV_ELEMS (B_*H_*NW_*P_*D_)   // 41,943,040

// Scratch
__device__ float  g_q[QKV_ELEMS];
__device__ float  g_k[QKV_ELEMS];
__device__ float  g_v[QKV_ELEMS];
__device__ __half g_xh[M_*E_];        // fp16 patches
__device__ __half g_wh[3][E_*E_];     // fp16 weights

__device__ __forceinline__ uint32_t smem_u32(const void* p) {
    uint32_t a;
    asm("{ .reg .u64 t; cvta.to.shared.u64 t, %1; cvt.u32.u64 %0, t; }" : "=r"(a) : "l"(p));
    return a;
}

#define CP_ASYNC16(dst, src) \
    asm volatile("cp.async.cg.shared.global [%0], [%1], 16;" :: "r"(dst), "l"(src))
#define CP_COMMIT()  asm volatile("cp.async.commit_group;" ::: "memory")
#define CP_WAIT(n)   asm volatile("cp.async.wait_group %0;" :: "n"(n) : "memory")

__device__ __forceinline__ void mma_f16(float* c, const uint32_t* a, const uint32_t* b) {
    asm volatile(
        "mma.sync.aligned.m16n8k16.row.col.f32.f16.f16.f32 "
        "{%0,%1,%2,%3}, {%4,%5,%6,%7}, {%8,%9}, {%0,%1,%2,%3};"
        : "+f"(c[0]), "+f"(c[1]), "+f"(c[2]), "+f"(c[3])
        : "r"(a[0]), "r"(a[1]), "r"(a[2]), "r"(a[3]), "r"(b[0]), "r"(b[1]));
}

// ---------------------------------------------------------------------------
// Prepass: convert patches + weights to fp16 (rn).
// ---------------------------------------------------------------------------
#define XN4 (M_*E_/4)
#define WN4 (E_*E_/4)
#define TOT4 (XN4 + 3*WN4)

__global__ __launch_bounds__(256) void prepass(
    const float* __restrict__ x,
    const float* __restrict__ wq, const float* __restrict__ wk,
    const float* __restrict__ wv)
{
    int gid = blockIdx.x * 256 + threadIdx.x;
    if (gid >= TOT4) return;
    const float* src;
    __half* dst;
    if (gid < XN4) { src = x; dst = g_xh; }
    else {
        int j = gid - XN4;
        int which = j / WN4;
        gid = j - which * WN4;
        src = (which == 0) ? wq : (which == 1) ? wk : wv;
        dst = g_wh[which];
    }
    float4 v = *(const float4*)(src + (size_t)gid * 4);
    __half2 h01 = __floats2half2_rn(v.x, v.y);
    __half2 h23 = __floats2half2_rn(v.z, v.w);
    uint2 u;
    u.x = *(uint32_t*)&h01;
    u.y = *(uint32_t*)&h23;
    *(uint2*)((char*)dst + (size_t)gid * 8) = u;
}

// ---------------------------------------------------------------------------
// QKV projection via fp16 mma.sync (m16n8k16).
// CTA 128x128, 8 warps (2m x 4n), warp tile 64x32, BK=32, double-buffered.
// Smem stride 40 halves (conflict-free fragment loads).
// ---------------------------------------------------------------------------
#define QST 40

__global__ __launch_bounds__(256, 2) void qkv_mma(
    const float* __restrict__ bq, const float* __restrict__ bk,
    const float* __restrict__ bv)
{
    __shared__ __half Asm[2][128][QST];
    __shared__ __half Bsm[2][128][QST];

    const __half* wgt; const float* bias; float* outp;
    if (blockIdx.z == 0)      { wgt = g_wh[0]; bias = bq; outp = g_q; }
    else if (blockIdx.z == 1) { wgt = g_wh[1]; bias = bk; outp = g_k; }
    else                      { wgt = g_wh[2]; bias = bv; outp = g_v; }

    const int m0 = blockIdx.x * 128;
    const int f0 = blockIdx.y * 128;
    const int tid = threadIdx.x;
    const int wid = tid >> 5;
    const int lane = tid & 31;
    const int g = lane >> 2;
    const int t = lane & 3;

    const int warp_m = (wid & 1) * 64;
    const int warp_n = (wid >> 1) * 32;

    const int srow = tid >> 1;              // 0..127
    const int sseg = (tid & 1) * 16;        // half-offset 0 or 16

    float c[4][4][4];
#pragma unroll
    for (int i = 0; i < 4; i++)
#pragma unroll
        for (int j = 0; j < 4; j++)
#pragma unroll
            for (int k = 0; k < 4; k++) c[i][j][k] = 0.0f;

    const __half* xa = g_xh + (size_t)m0 * E_;
    const __half* wa = wgt  + (size_t)f0 * E_;

#define STAGE(bufsel, koff)                                                     \
    {                                                                           \
        CP_ASYNC16(smem_u32(&Asm[bufsel][srow][sseg]),                          \
                   xa + (size_t)srow * E_ + (koff) + sseg);                     \
        CP_ASYNC16(smem_u32(&Asm[bufsel][srow][sseg + 8]),                      \
                   xa + (size_t)srow * E_ + (koff) + sseg + 8);                 \
        CP_ASYNC16(smem_u32(&Bsm[bufsel][srow][sseg]),                          \
                   wa + (size_t)srow * E_ + (koff) + sseg);                     \
        CP_ASYNC16(smem_u32(&Bsm[bufsel][srow][sseg + 8]),                      \
                   wa + (size_t)srow * E_ + (koff) + sseg + 8);                 \
        CP_COMMIT();                                                            \
    }

    STAGE(0, 0)

    int buf = 0;
    for (int kt = 0; kt < E_; kt += 32) {
        if (kt + 32 < E_) {
            STAGE(buf ^ 1, kt + 32)
            CP_WAIT(1);
        } else {
            CP_WAIT(0);
        }
        __syncthreads();

#pragma unroll
        for (int kk = 0; kk < 32; kk += 16) {
            uint32_t a[4][4], bfr[4][2];
#pragma unroll
            for (int tm = 0; tm < 4; tm++) {
                const __half* ap = &Asm[buf][warp_m + tm * 16 + g][kk + 2 * t];
                a[tm][0] = *(const uint32_t*)(ap);
                a[tm][1] = *(const uint32_t*)(ap + 8 * QST);
                a[tm][2] = *(const uint32_t*)(ap + 8);
                a[tm][3] = *(const uint32_t*)(ap + 8 * QST + 8);
            }
#pragma unroll
            for (int tn = 0; tn < 4; tn++) {
                const __half* bp = &Bsm[buf][warp_n + tn * 8 + g][kk + 2 * t];
                bfr[tn][0] = *(const uint32_t*)(bp);
                bfr[tn][1] = *(const uint32_t*)(bp + 8);
            }
#pragma unroll
            for (int tm = 0; tm < 4; tm++)
#pragma unroll
                for (int tn = 0; tn < 4; tn++)
                    mma_f16(c[tm][tn], a[tm], bfr[tn]);
        }
        __syncthreads();
        buf ^= 1;
    }
#undef STAGE

    // Epilogue: bias + scatter into [B,H,NW,P,D]
#pragma unroll
    for (int tm = 0; tm < 4; tm++) {
        const int mr0 = m0 + warp_m + tm * 16 + g;
#pragma unroll
        for (int rr = 0; rr < 2; rr++) {
            const int m = mr0 + rr * 8;
            const int bi  = m / (NW_ * P_);
            const int rem = m - bi * (NW_ * P_);
            const int ww  = rem / P_;
            const int p   = rem - ww * P_;
            const size_t rowbase = ((size_t)(bi * H_) * NW_ + ww) * P_ + p;
#pragma unroll
            for (int tn = 0; tn < 4; tn++) {
                const int col = f0 + warp_n + tn * 8 + t * 2;
                const int hh = col >> 6;
                const int d0 = col & 63;
                float2 o;
                o.x = c[tm][tn][rr * 2 + 0] + bias[col];
                o.y = c[tm][tn][rr * 2 + 1] + bias[col + 1];
                *(float2*)(outp + (rowbase + (size_t)hh * NW_ * P_) * D_ + d0) = o;
            }
        }
    }
}

// ---------------------------------------------------------------------------
// Attention with fp16 mma. One CTA (512 thr) per (b,h,w).
// bufA (89600 B): phase1 Qs h[160][72] + Ks h[192][72];
//                 phase2 Ps h[160][200] + Vt h[64][200]
// Ss f32[160][196] at offset 89600. Total 215040 B dynamic.
// ---------------------------------------------------------------------------
#define QS_STR 72
#define KS_STR 72
#define PS_STR 200
#define VT_STR 200
#define SS_STR 196
#define OFF_KS 23040
#define OFF_VT 64000
#define OFF_SS 89600
#define ATT_SMEM_BYTES (OFF_SS + 160 * SS_STR * 4)   // 215040

__global__ __launch_bounds__(512) void attn_mma(
    const float* __restrict__ pos_bias,
    float* __restrict__ out)
{
    extern __shared__ char smc[];
    __half* Qs = (__half*)smc;
    __half* Ks = (__half*)(smc + OFF_KS);
    __half* Ps = (__half*)smc;
    __half* Vt = (__half*)(smc + OFF_VT);
    float*  Ss = (float*)(smc + OFF_SS);
    __shared__ float pb[19 * 31];
    __shared__ float rsum[160];

    const int w = blockIdx.x, h = blockIdx.y, b = blockIdx.z;
    const int tid = threadIdx.x;
    const int lane = tid & 31, warp = tid >> 5;
    const int g = lane >> 2, t = lane & 3;
    const float NEG_INF = __int_as_float(0xff800000);

    for (int i = tid; i < 19 * 31; i += 512) pb[i] = pos_bias[i];

    const size_t base = ((size_t)(b * H_ + h) * NW_ + w) * (P_ * D_);
    const float* qg = g_q + base;
    const float* kg = g_k + base;
    const float* vg = g_v + base;

    // Phase 1: stage Q (scaled) and K as fp16
    for (int i = tid; i < P_ * D_ / 4; i += 512) {
        int e = i * 4;
        int p = e >> 6;
        int d = e & 63;
        float4 q4 = *(const float4*)(qg + e);
        __half2 qa = __floats2half2_rn(q4.x * 0.125f, q4.y * 0.125f);
        __half2 qb = __floats2half2_rn(q4.z * 0.125f, q4.w * 0.125f);
        uint2 uq; uq.x = *(uint32_t*)&qa; uq.y = *(uint32_t*)&qb;
        *(uint2*)(Qs + p * QS_STR + d) = uq;
        float4 k4 = *(const float4*)(kg + e);
        __half2 ka = __floats2half2_rn(k4.x, k4.y);
        __half2 kb = __floats2half2_rn(k4.z, k4.w);
        uint2 uk; uk.x = *(uint32_t*)&ka; uk.y = *(uint32_t*)&kb;
        *(uint2*)(Ks + p * KS_STR + d) = uk;
    }
    // zero pad K rows 160..191
    for (int i = tid; i < 32 * KS_STR / 2; i += 512)
        *(uint32_t*)((char*)Ks + 160 * KS_STR * 2 + i * 4) = 0u;
    __syncthreads();

    // S = Q K^T : warp grid 2(m) x 8(n); warp tile 80 x 24, K=64 (4 ksteps)
    const int wmS = warp & 1, wnS = warp >> 1;
    const int mS = wmS * 80, nS = wnS * 24;
    float c[5][3][4];
#pragma unroll
    for (int i = 0; i < 5; i++)
#pragma unroll
        for (int j = 0; j < 3; j++)
#pragma unroll
            for (int k = 0; k < 4; k++) c[i][j][k] = 0.0f;

#pragma unroll
    for (int kk = 0; kk < 64; kk += 16) {
        uint32_t a[5][4], bf[3][2];
#pragma unroll
        for (int tm = 0; tm < 5; tm++) {
            const __half* ap = Qs + (mS + tm * 16 + g) * QS_STR + kk + 2 * t;
            a[tm][0] = *(const uint32_t*)(ap);
            a[tm][1] = *(const uint32_t*)(ap + 8 * QS_STR);
            a[tm][2] = *(const uint32_t*)(ap + 8);
            a[tm][3] = *(const uint32_t*)(ap + 8 * QS_STR + 8);
        }
#pragma unroll
        for (int tn = 0; tn < 3; tn++) {
            const __half* bp = Ks + (nS + tn * 8 + g) * KS_STR + kk + 2 * t;
            bf[tn][0] = *(const uint32_t*)(bp);
            bf[tn][1] = *(const uint32_t*)(bp + 8);
        }
#pragma unroll
        for (int tm = 0; tm < 5; tm++)
#pragma unroll
            for (int tn = 0; tn < 3; tn++)
                mma_f16(c[tm][tn], a[tm], bf[tn]);
    }

    // Bias + shift-mask -> Ss (fp32)
    const int wy = w >> 3, wx = w & 7;
#pragma unroll
    for (int tm = 0; tm < 5; tm++) {
#pragma unroll
        for (int rr = 0; rr < 2; rr++) {
            const int i = mS + tm * 16 + g + rr * 8;
            const int vi = i >> 4, hi = i & 15;
#pragma unroll
            for (int tn = 0; tn < 3; tn++) {
#pragma unroll
                for (int e2 = 0; e2 < 2; e2++) {
                    const int j = nS + tn * 8 + t * 2 + e2;
                    float sv;
                    if (j >= P_) sv = NEG_INF;
                    else {
                        const int vj = j >> 4, hj = j & 15;
                        int dv = vj - vi + 19; if (dv >= 19) dv -= 19;
                        int dh = hj - hi + 31; if (dh >= 31) dh -= 31;
                        float s = c[tm][tn][rr * 2 + e2] + pb[dv * 31 + dh];
                        bool msk = ((wy == 7) && ((vi < 5) != (vj < 5))) ||
                                   ((wx == 7) && ((hi < 8) != (hj < 8)));
                        sv = msk ? NEG_INF : s;
                    }
                    Ss[i * SS_STR + j] = sv;
                }
            }
        }
    }
    __syncthreads();

    // Softmax over 192 cols (fp32), exp kept in Ss
    for (int r = warp; r < P_; r += 16) {
        float vals[6];
        float mx = NEG_INF;
#pragma unroll
        for (int s6 = 0; s6 < 6; s6++) {
            vals[s6] = Ss[r * SS_STR + lane + 32 * s6];
            mx = fmaxf(mx, vals[s6]);
        }
#pragma unroll
        for (int o = 16; o > 0; o >>= 1)
            mx = fmaxf(mx, __shfl_xor_sync(0xffffffffu, mx, o));
        float sum = 0.0f;
#pragma unroll
        for (int s6 = 0; s6 < 6; s6++) {
            float e = __expf(vals[s6] - mx);
            vals[s6] = e;
            sum += e;
        }
#pragma unroll
        for (int o = 16; o > 0; o >>= 1)
            sum += __shfl_xor_sync(0xffffffffu, sum, o);
#pragma unroll
        for (int s6 = 0; s6 < 6; s6++)
            Ss[r * SS_STR + lane + 32 * s6] = vals[s6];
        if (lane == 0) rsum[r] = 1.0f / sum;
    }
    __syncthreads();

    // Phase 2: stage Vt (half, transposed, padded) and convert P -> Ps (half)
    for (int i = tid; i < P_ * D_ / 4; i += 512) {
        int e = i * 4;
        int p = e >> 6;
        int d = e & 63;
        float4 v4 = *(const float4*)(vg + e);
        Vt[(d + 0) * VT_STR + p] = __float2half_rn(v4.x);
        Vt[(d + 1) * VT_STR + p] = __float2half_rn(v4.y);
        Vt[(d + 2) * VT_STR + p] = __float2half_rn(v4.z);
        Vt[(d + 3) * VT_STR + p] = __float2half_rn(v4.w);
    }
    for (int i = tid; i < 64 * 32; i += 512) {
        int d = i >> 5, pp = 160 + (i & 31);
        Vt[d * VT_STR + pp] = __float2half_rn(0.0f);
    }
    for (int i = tid; i < 160 * 96; i += 512) {
        int r = i / 96;
        int c2 = (i - r * 96) * 2;
        __half2 hp = __floats2half2_rn(Ss[r * SS_STR + c2], Ss[r * SS_STR + c2 + 1]);
        *(uint32_t*)((char*)Ps + (size_t)(r * PS_STR + c2) * 2) = *(uint32_t*)&hp;
    }
    __syncthreads();

    // O = P Vt^T : warp grid 2(m) x 8(n); warp tile 80 x 8, K=192 (12 ksteps)
    const int wmO = warp >> 3, wnO = warp & 7;
    const int mO = wmO * 80, nO = wnO * 8;
    float o[5][4];
#pragma unroll
    for (int i = 0; i < 5; i++)
#pragma unroll
        for (int k = 0; k < 4; k++) o[i][k] = 0.0f;

    for (int ks = 0; ks < 192; ks += 16) {
        uint32_t a[5][4], bf[2];
#pragma unroll
        for (int tm = 0; tm < 5; tm++) {
            const __half* ap = Ps + (mO + tm * 16 + g) * PS_STR + ks + 2 * t;
            a[tm][0] = *(const uint32_t*)(ap);
            a[tm][1] = *(const uint32_t*)(ap + 8 * PS_STR);
            a[tm][2] = *(const uint32_t*)(ap + 8);
            a[tm][3] = *(const uint32_t*)(ap + 8 * PS_STR + 8);
        }
        {
            const __half* bp = Vt + (nO + g) * VT_STR + ks + 2 * t;
            bf[0] = *(const uint32_t*)(bp);
            bf[1] = *(const uint32_t*)(bp + 8);
        }
#pragma unroll
        for (int tm = 0; tm < 5; tm++)
            mma_f16(o[tm], a[tm], bf);
    }

    // Epilogue: normalize, write out
#pragma unroll
    for (int tm = 0; tm < 5; tm++) {
#pragma unroll
        for (int rr = 0; rr < 2; rr++) {
            const int p = mO + tm * 16 + g + rr * 8;
            const float inv = rsum[p];
            float2 o2;
            o2.x = o[tm][rr * 2 + 0] * inv;
            o2.y = o[tm][rr * 2 + 1] * inv;
            *(float2*)(out + ((size_t)(b * NW_ + w) * P_ + p) * E_ + h * D_ + nO + t * 2) = o2;
        }
    }
}

// ---------------------------------------------------------------------------
extern "C" void kernel_launch(void* const* d_in, const int* in_sizes, int n_in,
                              void* d_out, int out_size)
{
    const float* patches  = (const float*)d_in[0];
    const float* wq       = (const float*)d_in[1];
    const float* bq       = (const float*)d_in[2];
    const float* wk       = (const float*)d_in[3];
    const float* bk       = (const float*)d_in[4];
    const float* wv       = (const float*)d_in[5];
    const float* bv       = (const float*)d_in[6];
    const float* pos_bias = (const float*)d_in[7];
    float* out            = (float*)d_out;

    prepass<<<(TOT4 + 255) / 256, 256>>>(patches, wq, wk, wv);

    dim3 g1(M_ / 128, E_ / 128, 3);   // (640, 4, 3)
    qkv_mma<<<g1, 256>>>(bq, bk, bv);

    cudaFuncSetAttribute(attn_mma,
                         cudaFuncAttributeMaxDynamicSharedMemorySize, ATT_SMEM_BYTES);
    dim3 g2(NW_, H_, B_);             // (64, 8, 8)
    attn_mma<<<g2, 512, ATT_SMEM_BYTES>>>(pos_bias, out);
}

// round 9
// speedup vs baseline: 1.6018x; 1.1204x over previous
#include <cuda_runtime.h>
#include <cuda_fp16.h>
#include <math.h>
#include <stdint.h>

#define B_  8
#define NW_ 64
#define P_  160
#define E_  512
#define H_  8
#define D_  64
#define M_  (B_*NW_*P_)               // 81920
#define QKV_ELEMS (B_*H_*NW_*P_*D_)   // 41,943,040

// Scratch (all fp16 now)
__device__ __half g_qh[QKV_ELEMS];
__device__ __half g_kh[QKV_ELEMS];
__device__ __half g_vh[QKV_ELEMS];
__device__ __half g_xh[M_*E_];
__device__ __half g_wh[3][E_*E_];

__device__ __forceinline__ uint32_t smem_u32(const void* p) {
    uint32_t a;
    asm("{ .reg .u64 t; cvta.to.shared.u64 t, %1; cvt.u32.u64 %0, t; }" : "=r"(a) : "l"(p));
    return a;
}

#define CP_ASYNC16(dst, src) \
    asm volatile("cp.async.cg.shared.global [%0], [%1], 16;" :: "r"(dst), "l"(src))
#define CP_COMMIT()  asm volatile("cp.async.commit_group;" ::: "memory")
#define CP_WAIT(n)   asm volatile("cp.async.wait_group %0;" :: "n"(n) : "memory")

__device__ __forceinline__ void mma_f16(float* c, const uint32_t* a, const uint32_t* b) {
    asm volatile(
        "mma.sync.aligned.m16n8k16.row.col.f32.f16.f16.f32 "
        "{%0,%1,%2,%3}, {%4,%5,%6,%7}, {%8,%9}, {%0,%1,%2,%3};"
        : "+f"(c[0]), "+f"(c[1]), "+f"(c[2]), "+f"(c[3])
        : "r"(a[0]), "r"(a[1]), "r"(a[2]), "r"(a[3]), "r"(b[0]), "r"(b[1]));
}
__device__ __forceinline__ void ldsm_x4(uint32_t* r, uint32_t addr) {
    asm volatile("ldmatrix.sync.aligned.m8n8.x4.shared.b16 {%0,%1,%2,%3}, [%4];"
        : "=r"(r[0]), "=r"(r[1]), "=r"(r[2]), "=r"(r[3]) : "r"(addr));
}
__device__ __forceinline__ void ldsm_x2(uint32_t* r, uint32_t addr) {
    asm volatile("ldmatrix.sync.aligned.m8n8.x2.shared.b16 {%0,%1}, [%2];"
        : "=r"(r[0]), "=r"(r[1]) : "r"(addr));
}
__device__ __forceinline__ void ldsm_x2t(uint32_t* r, uint32_t addr) {
    asm volatile("ldmatrix.sync.aligned.m8n8.x2.trans.shared.b16 {%0,%1}, [%2];"
        : "=r"(r[0]), "=r"(r[1]) : "r"(addr));
}

// ---------------------------------------------------------------------------
// Prepass: fp32 -> fp16; wq scaled by 0.125 (exact) so Q comes pre-scaled.
// ---------------------------------------------------------------------------
#define XN4 (M_*E_/4)
#define WN4 (E_*E_/4)
#define TOT4 (XN4 + 3*WN4)

__global__ __launch_bounds__(256) void prepass(
    const float* __restrict__ x,
    const float* __restrict__ wq, const float* __restrict__ wk,
    const float* __restrict__ wv)
{
    int gid = blockIdx.x * 256 + threadIdx.x;
    if (gid >= TOT4) return;
    const float* src;
    __half* dst;
    float scl = 1.0f;
    if (gid < XN4) { src = x; dst = g_xh; }
    else {
        int j = gid - XN4;
        int which = j / WN4;
        gid = j - which * WN4;
        src = (which == 0) ? wq : (which == 1) ? wk : wv;
        dst = g_wh[which];
        if (which == 0) scl = 0.125f;
    }
    float4 v = *(const float4*)(src + (size_t)gid * 4);
    __half2 h01 = __floats2half2_rn(v.x * scl, v.y * scl);
    __half2 h23 = __floats2half2_rn(v.z * scl, v.w * scl);
    uint2 u;
    u.x = *(uint32_t*)&h01;
    u.y = *(uint32_t*)&h23;
    *(uint2*)((char*)dst + (size_t)gid * 8) = u;
}

// ---------------------------------------------------------------------------
// QKV projection via fp16 mma.sync; outputs fp16 into [B,H,NW,P,D].
// CTA 128x128, 8 warps (2m x 4n), warp tile 64x32, BK=32, double-buffered.
// ---------------------------------------------------------------------------
#define QST 40

__global__ __launch_bounds__(256, 2) void qkv_mma(
    const float* __restrict__ bq, const float* __restrict__ bk,
    const float* __restrict__ bv)
{
    __shared__ __half Asm[2][128][QST];
    __shared__ __half Bsm[2][128][QST];

    const __half* wgt; const float* bias; __half* outp; float bscl;
    if (blockIdx.z == 0)      { wgt = g_wh[0]; bias = bq; outp = g_qh; bscl = 0.125f; }
    else if (blockIdx.z == 1) { wgt = g_wh[1]; bias = bk; outp = g_kh; bscl = 1.0f; }
    else                      { wgt = g_wh[2]; bias = bv; outp = g_vh; bscl = 1.0f; }

    const int m0 = blockIdx.x * 128;
    const int f0 = blockIdx.y * 128;
    const int tid = threadIdx.x;
    const int wid = tid >> 5;
    const int lane = tid & 31;
    const int g = lane >> 2;
    const int t = lane & 3;

    const int warp_m = (wid & 1) * 64;
    const int warp_n = (wid >> 1) * 32;

    const int srow = tid >> 1;
    const int sseg = (tid & 1) * 16;

    float c[4][4][4];
#pragma unroll
    for (int i = 0; i < 4; i++)
#pragma unroll
        for (int j = 0; j < 4; j++)
#pragma unroll
            for (int k = 0; k < 4; k++) c[i][j][k] = 0.0f;

    const __half* xa = g_xh + (size_t)m0 * E_;
    const __half* wa = wgt  + (size_t)f0 * E_;

#define STAGE(bufsel, koff)                                                     \
    {                                                                           \
        CP_ASYNC16(smem_u32(&Asm[bufsel][srow][sseg]),                          \
                   xa + (size_t)srow * E_ + (koff) + sseg);                     \
        CP_ASYNC16(smem_u32(&Asm[bufsel][srow][sseg + 8]),                      \
                   xa + (size_t)srow * E_ + (koff) + sseg + 8);                 \
        CP_ASYNC16(smem_u32(&Bsm[bufsel][srow][sseg]),                          \
                   wa + (size_t)srow * E_ + (koff) + sseg);                     \
        CP_ASYNC16(smem_u32(&Bsm[bufsel][srow][sseg + 8]),                      \
                   wa + (size_t)srow * E_ + (koff) + sseg + 8);                 \
        CP_COMMIT();                                                            \
    }

    STAGE(0, 0)

    int buf = 0;
    for (int kt = 0; kt < E_; kt += 32) {
        if (kt + 32 < E_) {
            STAGE(buf ^ 1, kt + 32)
            CP_WAIT(1);
        } else {
            CP_WAIT(0);
        }
        __syncthreads();

#pragma unroll
        for (int kk = 0; kk < 32; kk += 16) {
            uint32_t a[4][4], bfr[4][2];
#pragma unroll
            for (int tm = 0; tm < 4; tm++) {
                const __half* ap = &Asm[buf][warp_m + tm * 16 + g][kk + 2 * t];
                a[tm][0] = *(const uint32_t*)(ap);
                a[tm][1] = *(const uint32_t*)(ap + 8 * QST);
                a[tm][2] = *(const uint32_t*)(ap + 8);
                a[tm][3] = *(const uint32_t*)(ap + 8 * QST + 8);
            }
#pragma unroll
            for (int tn = 0; tn < 4; tn++) {
                const __half* bp = &Bsm[buf][warp_n + tn * 8 + g][kk + 2 * t];
                bfr[tn][0] = *(const uint32_t*)(bp);
                bfr[tn][1] = *(const uint32_t*)(bp + 8);
            }
#pragma unroll
            for (int tm = 0; tm < 4; tm++)
#pragma unroll
                for (int tn = 0; tn < 4; tn++)
                    mma_f16(c[tm][tn], a[tm], bfr[tn]);
        }
        __syncthreads();
        buf ^= 1;
    }
#undef STAGE

    // Epilogue: bias (scaled) + fp16 store into [B,H,NW,P,D]
#pragma unroll
    for (int tm = 0; tm < 4; tm++) {
        const int mr0 = m0 + warp_m + tm * 16 + g;
#pragma unroll
        for (int rr = 0; rr < 2; rr++) {
            const int m = mr0 + rr * 8;
            const int bi  = m / (NW_ * P_);
            const int rem = m - bi * (NW_ * P_);
            const int ww  = rem / P_;
            const int p   = rem - ww * P_;
            const size_t rowbase = ((size_t)(bi * H_) * NW_ + ww) * P_ + p;
#pragma unroll
            for (int tn = 0; tn < 4; tn++) {
                const int col = f0 + warp_n + tn * 8 + t * 2;
                const int hh = col >> 6;
                const int d0 = col & 63;
                __half2 o = __floats2half2_rn(
                    c[tm][tn][rr * 2 + 0] + bias[col] * bscl,
                    c[tm][tn][rr * 2 + 1] + bias[col + 1] * bscl);
                *(uint32_t*)(outp + (rowbase + (size_t)hh * NW_ * P_) * D_ + d0) =
                    *(uint32_t*)&o;
            }
        }
    }
}

// ---------------------------------------------------------------------------
// Attention with fp16 mma + ldmatrix. One CTA (512 thr) per (b,h,w).
// Layout (dynamic smem, bytes):
//   [0, 64000):      phase1 Qs h[160][72] @0, Ks h[192][72] @23040
//                    phase2 Ps h[160][200] @0
//   [64000, 91648):  Vs h[192][72] (row-major, ldmatrix.trans for B)
//   [91648, 217088): Ss f32[160][196]
// ---------------------------------------------------------------------------
#define QS_STR 72
#define KS_STR 72
#define VS_STR 72
#define PS_STR 200
#define SS_STR 196
#define OFF_KS 23040
#define OFF_VS 64000
#define OFF_SS 91648
#define ATT_SMEM_BYTES (OFF_SS + 160 * SS_STR * 4)   // 217088

__global__ __launch_bounds__(512) void attn_mma(
    const float* __restrict__ pos_bias,
    float* __restrict__ out)
{
    extern __shared__ char smc[];
    __half* Qs = (__half*)smc;
    __half* Ks = (__half*)(smc + OFF_KS);
    __half* Ps = (__half*)smc;
    __half* Vs = (__half*)(smc + OFF_VS);
    float*  Ss = (float*)(smc + OFF_SS);
    __shared__ float pb[19 * 31];
    __shared__ float rsum[160];

    const int w = blockIdx.x, h = blockIdx.y, b = blockIdx.z;
    const int tid = threadIdx.x;
    const int lane = tid & 31, warp = tid >> 5;
    const int g = lane >> 2, t = lane & 3;
    const float NEG_INF = __int_as_float(0xff800000);

    for (int i = tid; i < 19 * 31; i += 512) pb[i] = pos_bias[i];

    const size_t base = ((size_t)(b * H_ + h) * NW_ + w) * (P_ * D_);
    const __half* qg = g_qh + base;
    const __half* kg = g_kh + base;
    const __half* vg = g_vh + base;

    // Stage Q/K/V (pure half copies, fully coalesced)
    for (int i = tid; i < P_ * D_ / 8; i += 512) {
        int p = i >> 3;
        int d = (i & 7) * 8;
        uint4 uq = *(const uint4*)(qg + p * D_ + d);
        *(uint4*)(Qs + p * QS_STR + d) = uq;
        uint4 uk = *(const uint4*)(kg + p * D_ + d);
        *(uint4*)(Ks + p * KS_STR + d) = uk;
        uint4 uv = *(const uint4*)(vg + p * D_ + d);
        *(uint4*)(Vs + p * VS_STR + d) = uv;
    }
    // zero pad rows 160..191 of K and V
    for (int i = tid; i < 32 * KS_STR / 2; i += 512) {
        *(uint32_t*)((char*)Ks + 160 * KS_STR * 2 + i * 4) = 0u;
        *(uint32_t*)((char*)Vs + 160 * VS_STR * 2 + i * 4) = 0u;
    }
    __syncthreads();

    const uint32_t qbase = smem_u32(Qs);
    const uint32_t kbase = smem_u32(Ks);
    const uint32_t vbase = smem_u32(Vs);
    const uint32_t psbase = smem_u32(Ps);

    // S = Q K^T : warp grid 2(m) x 8(n); warp tile 80 x 24, K=64
    const int wmS = warp & 1, wnS = warp >> 1;
    const int mS = wmS * 80, nS = wnS * 24;
    float c[5][3][4];
#pragma unroll
    for (int i = 0; i < 5; i++)
#pragma unroll
        for (int j = 0; j < 3; j++)
#pragma unroll
            for (int k = 0; k < 4; k++) c[i][j][k] = 0.0f;

#pragma unroll
    for (int kk = 0; kk < 64; kk += 16) {
        uint32_t a[5][4], bf[3][2];
#pragma unroll
        for (int tm = 0; tm < 5; tm++) {
            int arow = mS + tm * 16 + (lane & 15);
            int acol = kk + (lane >> 4) * 8;
            ldsm_x4(a[tm], qbase + (uint32_t)(arow * QS_STR + acol) * 2);
        }
#pragma unroll
        for (int tn = 0; tn < 3; tn++) {
            int brow = nS + tn * 8 + (lane & 7);
            int bcol = kk + ((lane >> 3) & 1) * 8;
            ldsm_x2(bf[tn], kbase + (uint32_t)(brow * KS_STR + bcol) * 2);
        }
#pragma unroll
        for (int tm = 0; tm < 5; tm++)
#pragma unroll
            for (int tn = 0; tn < 3; tn++)
                mma_f16(c[tm][tn], a[tm], bf[tn]);
    }

    // Bias + shift-mask -> Ss (fp32)
    const int wy = w >> 3, wx = w & 7;
#pragma unroll
    for (int tm = 0; tm < 5; tm++) {
#pragma unroll
        for (int rr = 0; rr < 2; rr++) {
            const int i = mS + tm * 16 + g + rr * 8;
            const int vi = i >> 4, hi = i & 15;
#pragma unroll
            for (int tn = 0; tn < 3; tn++) {
#pragma unroll
                for (int e2 = 0; e2 < 2; e2++) {
                    const int j = nS + tn * 8 + t * 2 + e2;
                    float sv;
                    if (j >= P_) sv = NEG_INF;
                    else {
                        const int vj = j >> 4, hj = j & 15;
                        int dv = vj - vi + 19; if (dv >= 19) dv -= 19;
                        int dh = hj - hi + 31; if (dh >= 31) dh -= 31;
                        float s = c[tm][tn][rr * 2 + e2] + pb[dv * 31 + dh];
                        bool msk = ((wy == 7) && ((vi < 5) != (vj < 5))) ||
                                   ((wx == 7) && ((hi < 8) != (hj < 8)));
                        sv = msk ? NEG_INF : s;
                    }
                    Ss[i * SS_STR + j] = sv;
                }
            }
        }
    }
    __syncthreads();

    // Softmax over 192 cols; write exp directly as half2 into Ps
    for (int r = warp; r < P_; r += 16) {
        float2 v2[3];
        float mx = NEG_INF;
#pragma unroll
        for (int s3 = 0; s3 < 3; s3++) {
            v2[s3] = *(const float2*)&Ss[r * SS_STR + 2 * lane + 64 * s3];
            mx = fmaxf(mx, fmaxf(v2[s3].x, v2[s3].y));
        }
#pragma unroll
        for (int o = 16; o > 0; o >>= 1)
            mx = fmaxf(mx, __shfl_xor_sync(0xffffffffu, mx, o));
        float sum = 0.0f;
#pragma unroll
        for (int s3 = 0; s3 < 3; s3++) {
            v2[s3].x = __expf(v2[s3].x - mx);
            v2[s3].y = __expf(v2[s3].y - mx);
            sum += v2[s3].x + v2[s3].y;
        }
#pragma unroll
        for (int o = 16; o > 0; o >>= 1)
            sum += __shfl_xor_sync(0xffffffffu, sum, o);
#pragma unroll
        for (int s3 = 0; s3 < 3; s3++) {
            __half2 hp = __floats2half2_rn(v2[s3].x, v2[s3].y);
            *(uint32_t*)(Ps + r * PS_STR + 2 * lane + 64 * s3) = *(uint32_t*)&hp;
        }
        if (lane == 0) rsum[r] = 1.0f / sum;
    }
    __syncthreads();

    // O = P V : warp grid 2(m) x 8(n); warp tile 80 x 8, K=192
    const int wmO = warp >> 3, wnO = warp & 7;
    const int mO = wmO * 80, nO = wnO * 8;
    float o[5][4];
#pragma unroll
    for (int i = 0; i < 5; i++)
#pragma unroll
        for (int k = 0; k < 4; k++) o[i][k] = 0.0f;

    for (int ks = 0; ks < 192; ks += 16) {
        uint32_t a[5][4], bf[2];
#pragma unroll
        for (int tm = 0; tm < 5; tm++) {
            int prow = mO + tm * 16 + (lane & 15);
            int pcol = ks + (lane >> 4) * 8;
            ldsm_x4(a[tm], psbase + (uint32_t)(prow * PS_STR + pcol) * 2);
        }
        {
            int vrow = ks + (lane & 15);
            ldsm_x2t(bf, vbase + (uint32_t)(vrow * VS_STR + nO) * 2);
        }
#pragma unroll
        for (int tm = 0; tm < 5; tm++)
            mma_f16(o[tm], a[tm], bf);
    }

    // Epilogue: normalize, write out (fp32)
#pragma unroll
    for (int tm = 0; tm < 5; tm++) {
#pragma unroll
        for (int rr = 0; rr < 2; rr++) {
            const int p = mO + tm * 16 + g + rr * 8;
            const float inv = rsum[p];
            float2 o2;
            o2.x = o[tm][rr * 2 + 0] * inv;
            o2.y = o[tm][rr * 2 + 1] * inv;
            *(float2*)(out + ((size_t)(b * NW_ + w) * P_ + p) * E_ + h * D_ + nO + t * 2) = o2;
        }
    }
}

// ---------------------------------------------------------------------------
extern "C" void kernel_launch(void* const* d_in, const int* in_sizes, int n_in,
                              void* d_out, int out_size)
{
    const float* patches  = (const float*)d_in[0];
    const float* wq       = (const float*)d_in[1];
    const float* bq       = (const float*)d_in[2];
    const float* wk       = (const float*)d_in[3];
    const float* bk       = (const float*)d_in[4];
    const float* wv       = (const float*)d_in[5];
    const float* bv       = (const float*)d_in[6];
    const float* pos_bias = (const float*)d_in[7];
    float* out            = (float*)d_out;

    prepass<<<(TOT4 + 255) / 256, 256>>>(patches, wq, wk, wv);

    dim3 g1(M_ / 128, E_ / 128, 3);   // (640, 4, 3)
    qkv_mma<<<g1, 256>>>(bq, bk, bv);

    cudaFuncSetAttribute(attn_mma,
                         cudaFuncAttributeMaxDynamicSharedMemorySize, ATT_SMEM_BYTES);
    dim3 g2(NW_, H_, B_);             // (64, 8, 8)
    attn_mma<<<g2, 512, ATT_SMEM_BYTES>>>(pos_bias, out);
}

// round 11
// speedup vs baseline: 1.6578x; 1.0350x over previous
#include <cuda_runtime.h>
#include <cuda_fp16.h>
#include <math.h>
#include <stdint.h>

#define B_  8
#define NW_ 64
#define P_  160
#define E_  512
#define H_  8
#define D_  64
#define M_  (B_*NW_*P_)               // 81920
#define QKV_ELEMS (B_*H_*NW_*P_*D_)   // 41,943,040

// Scratch (all fp16)
__device__ __half g_qh[QKV_ELEMS];
__device__ __half g_kh[QKV_ELEMS];
__device__ __half g_vh[QKV_ELEMS];
__device__ __half g_xh[M_*E_];
__device__ __half g_wh[3][E_*E_];

__device__ __forceinline__ uint32_t smem_u32(const void* p) {
    uint32_t a;
    asm("{ .reg .u64 t; cvta.to.shared.u64 t, %1; cvt.u32.u64 %0, t; }" : "=r"(a) : "l"(p));
    return a;
}

#define CP_ASYNC16(dst, src) \
    asm volatile("cp.async.cg.shared.global [%0], [%1], 16;" :: "r"(dst), "l"(src))
#define CP_COMMIT()  asm volatile("cp.async.commit_group;" ::: "memory")
#define CP_WAIT(n)   asm volatile("cp.async.wait_group %0;" :: "n"(n) : "memory")

__device__ __forceinline__ void mma_f16(float* c, const uint32_t* a, const uint32_t* b) {
    asm volatile(
        "mma.sync.aligned.m16n8k16.row.col.f32.f16.f16.f32 "
        "{%0,%1,%2,%3}, {%4,%5,%6,%7}, {%8,%9}, {%0,%1,%2,%3};"
        : "+f"(c[0]), "+f"(c[1]), "+f"(c[2]), "+f"(c[3])
        : "r"(a[0]), "r"(a[1]), "r"(a[2]), "r"(a[3]), "r"(b[0]), "r"(b[1]));
}
__device__ __forceinline__ void ldsm_x4(uint32_t* r, uint32_t addr) {
    asm volatile("ldmatrix.sync.aligned.m8n8.x4.shared.b16 {%0,%1,%2,%3}, [%4];"
        : "=r"(r[0]), "=r"(r[1]), "=r"(r[2]), "=r"(r[3]) : "r"(addr));
}
__device__ __forceinline__ void ldsm_x2(uint32_t* r, uint32_t addr) {
    asm volatile("ldmatrix.sync.aligned.m8n8.x2.shared.b16 {%0,%1}, [%2];"
        : "=r"(r[0]), "=r"(r[1]) : "r"(addr));
}
__device__ __forceinline__ void ldsm_x2t(uint32_t* r, uint32_t addr) {
    asm volatile("ldmatrix.sync.aligned.m8n8.x2.trans.shared.b16 {%0,%1}, [%2];"
        : "=r"(r[0]), "=r"(r[1]) : "r"(addr));
}

// ---------------------------------------------------------------------------
// Prepass: fp32 -> fp16; wq scaled by 0.125 (exact power of 2).
// ---------------------------------------------------------------------------
#define XN4 (M_*E_/4)
#define WN4 (E_*E_/4)
#define TOT4 (XN4 + 3*WN4)

__global__ __launch_bounds__(256) void prepass(
    const float* __restrict__ x,
    const float* __restrict__ wq, const float* __restrict__ wk,
    const float* __restrict__ wv)
{
    int gid = blockIdx.x * 256 + threadIdx.x;
    if (gid >= TOT4) return;
    const float* src;
    __half* dst;
    float scl = 1.0f;
    if (gid < XN4) { src = x; dst = g_xh; }
    else {
        int j = gid - XN4;
        int which = j / WN4;
        gid = j - which * WN4;
        src = (which == 0) ? wq : (which == 1) ? wk : wv;
        dst = g_wh[which];
        if (which == 0) scl = 0.125f;
    }
    float4 v = *(const float4*)(src + (size_t)gid * 4);
    __half2 h01 = __floats2half2_rn(v.x * scl, v.y * scl);
    __half2 h23 = __floats2half2_rn(v.z * scl, v.w * scl);
    uint2 u;
    u.x = *(uint32_t*)&h01;
    u.y = *(uint32_t*)&h23;
    *(uint2*)((char*)dst + (size_t)gid * 8) = u;
}

// ---------------------------------------------------------------------------
// QKV projection via fp16 mma.sync (unchanged from R9).
// ---------------------------------------------------------------------------
#define QST 40

__global__ __launch_bounds__(256, 2) void qkv_mma(
    const float* __restrict__ bq, const float* __restrict__ bk,
    const float* __restrict__ bv)
{
    __shared__ __half Asm[2][128][QST];
    __shared__ __half Bsm[2][128][QST];

    const __half* wgt; const float* bias; __half* outp; float bscl;
    if (blockIdx.z == 0)      { wgt = g_wh[0]; bias = bq; outp = g_qh; bscl = 0.125f; }
    else if (blockIdx.z == 1) { wgt = g_wh[1]; bias = bk; outp = g_kh; bscl = 1.0f; }
    else                      { wgt = g_wh[2]; bias = bv; outp = g_vh; bscl = 1.0f; }

    const int m0 = blockIdx.x * 128;
    const int f0 = blockIdx.y * 128;
    const int tid = threadIdx.x;
    const int wid = tid >> 5;
    const int lane = tid & 31;
    const int g = lane >> 2;
    const int t = lane & 3;

    const int warp_m = (wid & 1) * 64;
    const int warp_n = (wid >> 1) * 32;

    const int srow = tid >> 1;
    const int sseg = (tid & 1) * 16;

    float c[4][4][4];
#pragma unroll
    for (int i = 0; i < 4; i++)
#pragma unroll
        for (int j = 0; j < 4; j++)
#pragma unroll
            for (int k = 0; k < 4; k++) c[i][j][k] = 0.0f;

    const __half* xa = g_xh + (size_t)m0 * E_;
    const __half* wa = wgt  + (size_t)f0 * E_;

#define STAGE(bufsel, koff)                                                     \
    {                                                                           \
        CP_ASYNC16(smem_u32(&Asm[bufsel][srow][sseg]),                          \
                   xa + (size_t)srow * E_ + (koff) + sseg);                     \
        CP_ASYNC16(smem_u32(&Asm[bufsel][srow][sseg + 8]),                      \
                   xa + (size_t)srow * E_ + (koff) + sseg + 8);                 \
        CP_ASYNC16(smem_u32(&Bsm[bufsel][srow][sseg]),                          \
                   wa + (size_t)srow * E_ + (koff) + sseg);                     \
        CP_ASYNC16(smem_u32(&Bsm[bufsel][srow][sseg + 8]),                      \
                   wa + (size_t)srow * E_ + (koff) + sseg + 8);                 \
        CP_COMMIT();                                                            \
    }

    STAGE(0, 0)

    int buf = 0;
    for (int kt = 0; kt < E_; kt += 32) {
        if (kt + 32 < E_) {
            STAGE(buf ^ 1, kt + 32)
            CP_WAIT(1);
        } else {
            CP_WAIT(0);
        }
        __syncthreads();

#pragma unroll
        for (int kk = 0; kk < 32; kk += 16) {
            uint32_t a[4][4], bfr[4][2];
#pragma unroll
            for (int tm = 0; tm < 4; tm++) {
                const __half* ap = &Asm[buf][warp_m + tm * 16 + g][kk + 2 * t];
                a[tm][0] = *(const uint32_t*)(ap);
                a[tm][1] = *(const uint32_t*)(ap + 8 * QST);
                a[tm][2] = *(const uint32_t*)(ap + 8);
                a[tm][3] = *(const uint32_t*)(ap + 8 * QST + 8);
            }
#pragma unroll
            for (int tn = 0; tn < 4; tn++) {
                const __half* bp = &Bsm[buf][warp_n + tn * 8 + g][kk + 2 * t];
                bfr[tn][0] = *(const uint32_t*)(bp);
                bfr[tn][1] = *(const uint32_t*)(bp + 8);
            }
#pragma unroll
            for (int tm = 0; tm < 4; tm++)
#pragma unroll
                for (int tn = 0; tn < 4; tn++)
                    mma_f16(c[tm][tn], a[tm], bfr[tn]);
        }
        __syncthreads();
        buf ^= 1;
    }
#undef STAGE

#pragma unroll
    for (int tm = 0; tm < 4; tm++) {
        const int mr0 = m0 + warp_m + tm * 16 + g;
#pragma unroll
        for (int rr = 0; rr < 2; rr++) {
            const int m = mr0 + rr * 8;
            const int bi  = m / (NW_ * P_);
            const int rem = m - bi * (NW_ * P_);
            const int ww  = rem / P_;
            const int p   = rem - ww * P_;
            const size_t rowbase = ((size_t)(bi * H_) * NW_ + ww) * P_ + p;
#pragma unroll
            for (int tn = 0; tn < 4; tn++) {
                const int col = f0 + warp_n + tn * 8 + t * 2;
                const int hh = col >> 6;
                const int d0 = col & 63;
                __half2 o = __floats2half2_rn(
                    c[tm][tn][rr * 2 + 0] + bias[col] * bscl,
                    c[tm][tn][rr * 2 + 1] + bias[col + 1] * bscl);
                *(uint32_t*)(outp + (rowbase + (size_t)hh * NW_ * P_) * D_ + d0) =
                    *(uint32_t*)&o;
            }
        }
    }
}

// ---------------------------------------------------------------------------
// Attention: 2 CTAs (256 thr) per (b,h,w), each owns 80 Q-rows, full K/V.
// Register-resident S + softmax; P exchanged via smem as fp16.
// smem: phase1 Qs h[80][72] @0, Ks h[192][72] @11520; Vs h[192][72] @39168
//       phase2 Ps h[80][200] @0 (overlays Q+K)
// ---------------------------------------------------------------------------
#define QS_STR 72
#define KS_STR 72
#define VS_STR 72
#define PS_STR 200
#define OFF_KS 11520
#define OFF_VS 39168
#define ATT_SMEM_BYTES (OFF_VS + 192 * VS_STR * 2)   // 66816

__global__ __launch_bounds__(256, 2) void attn_mma(
    const float* __restrict__ pos_bias,
    float* __restrict__ out)
{
    extern __shared__ char smc[];
    __half* Qs = (__half*)smc;
    __half* Ks = (__half*)(smc + OFF_KS);
    __half* Ps = (__half*)smc;
    __half* Vs = (__half*)(smc + OFF_VS);
    __shared__ __align__(16) float pb[19 * 31];
    __shared__ __align__(16) float wmax[80][8];
    __shared__ __align__(16) float wsum[80][8];

    const int w = blockIdx.x;
    const int h = blockIdx.y >> 1;
    const int mhalf = blockIdx.y & 1;
    const int b = blockIdx.z;
    const int tid = threadIdx.x;
    const int lane = tid & 31, warp = tid >> 5;   // 8 warps
    const int g = lane >> 2, t = lane & 3;
    const float NEG_INF = __int_as_float(0xff800000);

    for (int i = tid; i < 19 * 31; i += 256) pb[i] = pos_bias[i];

    const size_t base = ((size_t)(b * H_ + h) * NW_ + w) * (P_ * D_);
    const __half* qg = g_qh + base + (size_t)mhalf * 80 * D_;
    const __half* kg = g_kh + base;
    const __half* vg = g_vh + base;

    // Stage Q (80 rows), K, V (160 rows + 32 zero-pad rows)
    for (int i = tid; i < 80 * 8; i += 256) {
        int p = i >> 3, d = (i & 7) * 8;
        *(uint4*)(Qs + p * QS_STR + d) = *(const uint4*)(qg + p * D_ + d);
    }
    for (int i = tid; i < 160 * 8; i += 256) {
        int p = i >> 3, d = (i & 7) * 8;
        *(uint4*)(Ks + p * KS_STR + d) = *(const uint4*)(kg + p * D_ + d);
        *(uint4*)(Vs + p * VS_STR + d) = *(const uint4*)(vg + p * D_ + d);
    }
    for (int i = tid; i < 32 * KS_STR / 2; i += 256) {
        *(uint32_t*)((char*)Ks + 160 * KS_STR * 2 + i * 4) = 0u;
        *(uint32_t*)((char*)Vs + 160 * VS_STR * 2 + i * 4) = 0u;
    }
    __syncthreads();

    const uint32_t qbase = smem_u32(Qs);
    const uint32_t kbase = smem_u32(Ks);
    const uint32_t vbase = smem_u32(Vs);
    const uint32_t psbase = smem_u32(Ps);

    // S = Q K^T : all 8 warps cover rows 0..79; warp tile 80 x 24
    const int nS = warp * 24;
    float c[5][3][4];
#pragma unroll
    for (int i = 0; i < 5; i++)
#pragma unroll
        for (int j = 0; j < 3; j++)
#pragma unroll
            for (int k = 0; k < 4; k++) c[i][j][k] = 0.0f;

#pragma unroll
    for (int kk = 0; kk < 64; kk += 16) {
        uint32_t a[5][4], bf[3][2];
#pragma unroll
        for (int tm = 0; tm < 5; tm++) {
            int arow = tm * 16 + (lane & 15);
            int acol = kk + (lane >> 4) * 8;
            ldsm_x4(a[tm], qbase + (uint32_t)(arow * QS_STR + acol) * 2);
        }
#pragma unroll
        for (int tn = 0; tn < 3; tn++) {
            int brow = nS + tn * 8 + (lane & 7);
            int bcol = kk + ((lane >> 3) & 1) * 8;
            ldsm_x2(bf[tn], kbase + (uint32_t)(brow * KS_STR + bcol) * 2);
        }
#pragma unroll
        for (int tm = 0; tm < 5; tm++)
#pragma unroll
            for (int tn = 0; tn < 3; tn++)
                mma_f16(c[tm][tn], a[tm], bf[tn]);
    }

    // Bias + shift-mask in registers; per-warp row max -> wmax
    const int wy = w >> 3, wx = w & 7;
#pragma unroll
    for (int tm = 0; tm < 5; tm++) {
#pragma unroll
        for (int rr = 0; rr < 2; rr++) {
            const int i = tm * 16 + g + rr * 8;          // local row 0..79
            const int gi = mhalf * 80 + i;               // global row
            const int vi = gi >> 4, hi = gi & 15;
            float mx = NEG_INF;
#pragma unroll
            for (int tn = 0; tn < 3; tn++) {
#pragma unroll
                for (int e2 = 0; e2 < 2; e2++) {
                    const int j = nS + tn * 8 + t * 2 + e2;
                    float sv;
                    if (j >= P_) sv = NEG_INF;
                    else {
                        const int vj = j >> 4, hj = j & 15;
                        int dv = vj - vi + 19; if (dv >= 19) dv -= 19;
                        int dh = hj - hi + 31; if (dh >= 31) dh -= 31;
                        float s = c[tm][tn][rr * 2 + e2] + pb[dv * 31 + dh];
                        bool msk = ((wy == 7) && ((vi < 5) != (vj < 5))) ||
                                   ((wx == 7) && ((hi < 8) != (hj < 8)));
                        sv = msk ? NEG_INF : s;
                    }
                    c[tm][tn][rr * 2 + e2] = sv;
                    mx = fmaxf(mx, sv);
                }
            }
            mx = fmaxf(mx, __shfl_xor_sync(0xffffffffu, mx, 1));
            mx = fmaxf(mx, __shfl_xor_sync(0xffffffffu, mx, 2));
            if (t == 0) wmax[i][warp] = mx;
        }
    }
    __syncthreads();

    // exp + per-warp row sum + write P (half) to Ps
#pragma unroll
    for (int tm = 0; tm < 5; tm++) {
#pragma unroll
        for (int rr = 0; rr < 2; rr++) {
            const int i = tm * 16 + g + rr * 8;
            float4 m0 = *(const float4*)&wmax[i][0];
            float4 m1 = *(const float4*)&wmax[i][4];
            float mx = fmaxf(fmaxf(fmaxf(m0.x, m0.y), fmaxf(m0.z, m0.w)),
                             fmaxf(fmaxf(m1.x, m1.y), fmaxf(m1.z, m1.w)));
            float sum = 0.0f;
#pragma unroll
            for (int tn = 0; tn < 3; tn++) {
                float e0 = __expf(c[tm][tn][rr * 2 + 0] - mx);
                float e1 = __expf(c[tm][tn][rr * 2 + 1] - mx);
                sum += e0 + e1;
                __half2 hp = __floats2half2_rn(e0, e1);
                *(uint32_t*)(Ps + i * PS_STR + nS + tn * 8 + t * 2) = *(uint32_t*)&hp;
            }
            sum += __shfl_xor_sync(0xffffffffu, sum, 1);
            sum += __shfl_xor_sync(0xffffffffu, sum, 2);
            if (t == 0) wsum[i][warp] = sum;
        }
    }
    __syncthreads();

    // O = P V : warp tile 80 x 8, K=192
    const int nO = warp * 8;
    float o[5][4];
#pragma unroll
    for (int i = 0; i < 5; i++)
#pragma unroll
        for (int k = 0; k < 4; k++) o[i][k] = 0.0f;

    for (int ks = 0; ks < 192; ks += 16) {
        uint32_t a[5][4], bf[2];
#pragma unroll
        for (int tm = 0; tm < 5; tm++) {
            int prow = tm * 16 + (lane & 15);
            int pcol = ks + (lane >> 4) * 8;
            ldsm_x4(a[tm], psbase + (uint32_t)(prow * PS_STR + pcol) * 2);
        }
        {
            int vrow = ks + (lane & 15);
            ldsm_x2t(bf, vbase + (uint32_t)(vrow * VS_STR + nO) * 2);
        }
#pragma unroll
        for (int tm = 0; tm < 5; tm++)
            mma_f16(o[tm], a[tm], bf);
    }

    // Epilogue: normalize by row sum (Σ warp partials), write fp32
#pragma unroll
    for (int tm = 0; tm < 5; tm++) {
#pragma unroll
        for (int rr = 0; rr < 2; rr++) {
            const int p = tm * 16 + g + rr * 8;
            float4 s0 = *(const float4*)&wsum[p][0];
            float4 s1 = *(const float4*)&wsum[p][4];
            float inv = 1.0f / ((s0.x + s0.y + s0.z + s0.w) +
                                (s1.x + s1.y + s1.z + s1.w));
            const int gp = mhalf * 80 + p;
            float2 o2;
            o2.x = o[tm][rr * 2 + 0] * inv;
            o2.y = o[tm][rr * 2 + 1] * inv;
            *(float2*)(out + ((size_t)(b * NW_ + w) * P_ + gp) * E_ + h * D_ + nO + t * 2) = o2;
        }
    }
}

// ---------------------------------------------------------------------------
extern "C" void kernel_launch(void* const* d_in, const int* in_sizes, int n_in,
                              void* d_out, int out_size)
{
    const float* patches  = (const float*)d_in[0];
    const float* wq       = (const float*)d_in[1];
    const float* bq       = (const float*)d_in[2];
    const float* wk       = (const float*)d_in[3];
    const float* bk       = (const float*)d_in[4];
    const float* wv       = (const float*)d_in[5];
    const float* bv       = (const float*)d_in[6];
    const float* pos_bias = (const float*)d_in[7];
    float* out            = (float*)d_out;

    prepass<<<(TOT4 + 255) / 256, 256>>>(patches, wq, wk, wv);

    dim3 g1(M_ / 128, E_ / 128, 3);   // (640, 4, 3)
    qkv_mma<<<g1, 256>>>(bq, bk, bv);

    cudaFuncSetAttribute(attn_mma,
                         cudaFuncAttributeMaxDynamicSharedMemorySize, ATT_SMEM_BYTES);
    dim3 g2(NW_, H_ * 2, B_);         // (64, 16, 8) — y = h*2 + mhalf
    attn_mma<<<g2, 256, ATT_SMEM_BYTES>>>(pos_bias, out);
}

// round 12
// speedup vs baseline: 1.9697x; 1.1881x over previous
#include <cuda_runtime.h>
#include <cuda_fp16.h>
#include <math.h>
#include <stdint.h>

#define B_  8
#define NW_ 64
#define P_  160
#define E_  512
#define H_  8
#define D_  64
#define M_  (B_*NW_*P_)               // 81920
#define QKV_ELEMS (B_*H_*NW_*P_*D_)   // 41,943,040

// Scratch (all fp16)
__device__ __half g_qh[QKV_ELEMS];
__device__ __half g_kh[QKV_ELEMS];
__device__ __half g_vh[QKV_ELEMS];
__device__ __half g_xh[M_*E_];
__device__ __half g_wh[3][E_*E_];

__device__ __forceinline__ uint32_t smem_u32(const void* p) {
    uint32_t a;
    asm("{ .reg .u64 t; cvta.to.shared.u64 t, %1; cvt.u32.u64 %0, t; }" : "=r"(a) : "l"(p));
    return a;
}

#define CP_ASYNC16(dst, src) \
    asm volatile("cp.async.cg.shared.global [%0], [%1], 16;" :: "r"(dst), "l"(src))
#define CP_COMMIT()  asm volatile("cp.async.commit_group;" ::: "memory")
#define CP_WAIT(n)   asm volatile("cp.async.wait_group %0;" :: "n"(n) : "memory")

__device__ __forceinline__ void mma_f16(float* c, const uint32_t* a, const uint32_t* b) {
    asm volatile(
        "mma.sync.aligned.m16n8k16.row.col.f32.f16.f16.f32 "
        "{%0,%1,%2,%3}, {%4,%5,%6,%7}, {%8,%9}, {%0,%1,%2,%3};"
        : "+f"(c[0]), "+f"(c[1]), "+f"(c[2]), "+f"(c[3])
        : "r"(a[0]), "r"(a[1]), "r"(a[2]), "r"(a[3]), "r"(b[0]), "r"(b[1]));
}
__device__ __forceinline__ void ldsm_x4(uint32_t* r, uint32_t addr) {
    asm volatile("ldmatrix.sync.aligned.m8n8.x4.shared.b16 {%0,%1,%2,%3}, [%4];"
        : "=r"(r[0]), "=r"(r[1]), "=r"(r[2]), "=r"(r[3]) : "r"(addr));
}
__device__ __forceinline__ void ldsm_x2(uint32_t* r, uint32_t addr) {
    asm volatile("ldmatrix.sync.aligned.m8n8.x2.shared.b16 {%0,%1}, [%2];"
        : "=r"(r[0]), "=r"(r[1]) : "r"(addr));
}
__device__ __forceinline__ void ldsm_x4t(uint32_t* r, uint32_t addr) {
    asm volatile("ldmatrix.sync.aligned.m8n8.x4.trans.shared.b16 {%0,%1,%2,%3}, [%4];"
        : "=r"(r[0]), "=r"(r[1]), "=r"(r[2]), "=r"(r[3]) : "r"(addr));
}

// ---------------------------------------------------------------------------
// Prepass: fp32 -> fp16; wq scaled by 0.125 (exact power of 2).
// ---------------------------------------------------------------------------
#define XN4 (M_*E_/4)
#define WN4 (E_*E_/4)
#define TOT4 (XN4 + 3*WN4)

__global__ __launch_bounds__(256) void prepass(
    const float* __restrict__ x,
    const float* __restrict__ wq, const float* __restrict__ wk,
    const float* __restrict__ wv)
{
    int gid = blockIdx.x * 256 + threadIdx.x;
    if (gid >= TOT4) return;
    const float* src;
    __half* dst;
    float scl = 1.0f;
    if (gid < XN4) { src = x; dst = g_xh; }
    else {
        int j = gid - XN4;
        int which = j / WN4;
        gid = j - which * WN4;
        src = (which == 0) ? wq : (which == 1) ? wk : wv;
        dst = g_wh[which];
        if (which == 0) scl = 0.125f;
    }
    float4 v = *(const float4*)(src + (size_t)gid * 4);
    __half2 h01 = __floats2half2_rn(v.x * scl, v.y * scl);
    __half2 h23 = __floats2half2_rn(v.z * scl, v.w * scl);
    uint2 u;
    u.x = *(uint32_t*)&h01;
    u.y = *(uint32_t*)&h23;
    *(uint2*)((char*)dst + (size_t)gid * 8) = u;
}

// ---------------------------------------------------------------------------
// QKV projection via fp16 mma.sync (unchanged from R9/R11).
// ---------------------------------------------------------------------------
#define QST 40

__global__ __launch_bounds__(256, 2) void qkv_mma(
    const float* __restrict__ bq, const float* __restrict__ bk,
    const float* __restrict__ bv)
{
    __shared__ __half Asm[2][128][QST];
    __shared__ __half Bsm[2][128][QST];

    const __half* wgt; const float* bias; __half* outp; float bscl;
    if (blockIdx.z == 0)      { wgt = g_wh[0]; bias = bq; outp = g_qh; bscl = 0.125f; }
    else if (blockIdx.z == 1) { wgt = g_wh[1]; bias = bk; outp = g_kh; bscl = 1.0f; }
    else                      { wgt = g_wh[2]; bias = bv; outp = g_vh; bscl = 1.0f; }

    const int m0 = blockIdx.x * 128;
    const int f0 = blockIdx.y * 128;
    const int tid = threadIdx.x;
    const int wid = tid >> 5;
    const int lane = tid & 31;
    const int g = lane >> 2;
    const int t = lane & 3;

    const int warp_m = (wid & 1) * 64;
    const int warp_n = (wid >> 1) * 32;

    const int srow = tid >> 1;
    const int sseg = (tid & 1) * 16;

    float c[4][4][4];
#pragma unroll
    for (int i = 0; i < 4; i++)
#pragma unroll
        for (int j = 0; j < 4; j++)
#pragma unroll
            for (int k = 0; k < 4; k++) c[i][j][k] = 0.0f;

    const __half* xa = g_xh + (size_t)m0 * E_;
    const __half* wa = wgt  + (size_t)f0 * E_;

#define STAGE(bufsel, koff)                                                     \
    {                                                                           \
        CP_ASYNC16(smem_u32(&Asm[bufsel][srow][sseg]),                          \
                   xa + (size_t)srow * E_ + (koff) + sseg);                     \
        CP_ASYNC16(smem_u32(&Asm[bufsel][srow][sseg + 8]),                      \
                   xa + (size_t)srow * E_ + (koff) + sseg + 8);                 \
        CP_ASYNC16(smem_u32(&Bsm[bufsel][srow][sseg]),                          \
                   wa + (size_t)srow * E_ + (koff) + sseg);                     \
        CP_ASYNC16(smem_u32(&Bsm[bufsel][srow][sseg + 8]),                      \
                   wa + (size_t)srow * E_ + (koff) + sseg + 8);                 \
        CP_COMMIT();                                                            \
    }

    STAGE(0, 0)

    int buf = 0;
    for (int kt = 0; kt < E_; kt += 32) {
        if (kt + 32 < E_) {
            STAGE(buf ^ 1, kt + 32)
            CP_WAIT(1);
        } else {
            CP_WAIT(0);
        }
        __syncthreads();

#pragma unroll
        for (int kk = 0; kk < 32; kk += 16) {
            uint32_t a[4][4], bfr[4][2];
#pragma unroll
            for (int tm = 0; tm < 4; tm++) {
                const __half* ap = &Asm[buf][warp_m + tm * 16 + g][kk + 2 * t];
                a[tm][0] = *(const uint32_t*)(ap);
                a[tm][1] = *(const uint32_t*)(ap + 8 * QST);
                a[tm][2] = *(const uint32_t*)(ap + 8);
                a[tm][3] = *(const uint32_t*)(ap + 8 * QST + 8);
            }
#pragma unroll
            for (int tn = 0; tn < 4; tn++) {
                const __half* bp = &Bsm[buf][warp_n + tn * 8 + g][kk + 2 * t];
                bfr[tn][0] = *(const uint32_t*)(bp);
                bfr[tn][1] = *(const uint32_t*)(bp + 8);
            }
#pragma unroll
            for (int tm = 0; tm < 4; tm++)
#pragma unroll
                for (int tn = 0; tn < 4; tn++)
                    mma_f16(c[tm][tn], a[tm], bfr[tn]);
        }
        __syncthreads();
        buf ^= 1;
    }
#undef STAGE

#pragma unroll
    for (int tm = 0; tm < 4; tm++) {
        const int mr0 = m0 + warp_m + tm * 16 + g;
#pragma unroll
        for (int rr = 0; rr < 2; rr++) {
            const int m = mr0 + rr * 8;
            const int bi  = m / (NW_ * P_);
            const int rem = m - bi * (NW_ * P_);
            const int ww  = rem / P_;
            const int p   = rem - ww * P_;
            const size_t rowbase = ((size_t)(bi * H_) * NW_ + ww) * P_ + p;
#pragma unroll
            for (int tn = 0; tn < 4; tn++) {
                const int col = f0 + warp_n + tn * 8 + t * 2;
                const int hh = col >> 6;
                const int d0 = col & 63;
                __half2 o = __floats2half2_rn(
                    c[tm][tn][rr * 2 + 0] + bias[col] * bscl,
                    c[tm][tn][rr * 2 + 1] + bias[col + 1] * bscl);
                *(uint32_t*)(outp + (rowbase + (size_t)hh * NW_ * P_) * D_ + d0) =
                    *(uint32_t*)&o;
            }
        }
    }
}

// ---------------------------------------------------------------------------
// Attention v3: 1 CTA (320 thr, 10 warps) per (b,h,w).
// Each warp owns 16 Q-rows x ALL 160 key cols (20 n-tiles). S accums are
// reused in-register as PV A-fragments; softmax fully warp-local.
// smem: Qs h[160][72] | Ks h[160][72] | Vs h[160][72]  (69120 B)
// ---------------------------------------------------------------------------
#define AS_STR 72
#define OFF_K (160 * AS_STR)
#define OFF_V (320 * AS_STR)
#define ATT_SMEM_BYTES (480 * AS_STR * 2)   // 69120

__global__ __launch_bounds__(320, 1) void attn_mma(
    const float* __restrict__ pos_bias,
    float* __restrict__ out)
{
    extern __shared__ __half sm[];
    __half* Qs = sm;
    __half* Ks = sm + OFF_K;
    __half* Vs = sm + OFF_V;
    __shared__ __align__(16) float pb[19 * 31];

    const int w = blockIdx.x, h = blockIdx.y, b = blockIdx.z;
    const int tid = threadIdx.x;
    const int lane = tid & 31, warp = tid >> 5;   // 10 warps
    const int g = lane >> 2, t = lane & 3;
    const float NEG_INF = __int_as_float(0xff800000);

    for (int i = tid; i < 19 * 31; i += 320) pb[i] = pos_bias[i];

    const size_t base = ((size_t)(b * H_ + h) * NW_ + w) * (P_ * D_);
    const __half* qg = g_qh + base;
    const __half* kg = g_kh + base;
    const __half* vg = g_vh + base;

    // Stage Q/K/V: 160x64 halves each, stride 72; 1280 uint4 per array, 4/thread
#pragma unroll
    for (int it = 0; it < 4; it++) {
        int i = tid + it * 320;
        int p = i >> 3, d = (i & 7) * 8;
        *(uint4*)(Qs + p * AS_STR + d) = *(const uint4*)(qg + p * D_ + d);
        *(uint4*)(Ks + p * AS_STR + d) = *(const uint4*)(kg + p * D_ + d);
        *(uint4*)(Vs + p * AS_STR + d) = *(const uint4*)(vg + p * D_ + d);
    }
    __syncthreads();

    const uint32_t qbase = smem_u32(Qs);
    const uint32_t kbase = smem_u32(Ks);
    const uint32_t vbase = smem_u32(Vs);

    // ---- S = Q K^T : warp rows [warp*16, +16), 20 n-tiles, K=64
    float c[20][4];
#pragma unroll
    for (int j = 0; j < 20; j++)
#pragma unroll
        for (int k = 0; k < 4; k++) c[j][k] = 0.0f;

#pragma unroll
    for (int kk = 0; kk < 64; kk += 16) {
        uint32_t a[4];
        {
            int arow = warp * 16 + (lane & 15);
            int acol = kk + (lane >> 4) * 8;
            ldsm_x4(a, qbase + (uint32_t)(arow * AS_STR + acol) * 2);
        }
#pragma unroll
        for (int tn = 0; tn < 20; tn++) {
            uint32_t bf[2];
            int brow = tn * 8 + (lane & 7);
            int bcol = kk + ((lane >> 3) & 1) * 8;
            ldsm_x2(bf, kbase + (uint32_t)(brow * AS_STR + bcol) * 2);
            mma_f16(c[tn], a, bf);
        }
    }

    // ---- Bias + shift-mask + warp-local softmax (rows g and g+8 of this warp)
    const int wy = w >> 3, wx = w & 7;
    const int vi = warp;                 // both rows have v = warp (16 rows/v-block)
    const int hi_lo = g, hi_hi = g + 8;
    const bool vmask = (wy == 7);
    const bool hmask = (wx == 7);

    float mlo = NEG_INF, mhi = NEG_INF;
#pragma unroll
    for (int tn = 0; tn < 20; tn++) {
#pragma unroll
        for (int e2 = 0; e2 < 2; e2++) {
            const int j = tn * 8 + t * 2 + e2;
            const int vj = j >> 4, hj = j & 15;
            // row g
            {
                int dv = vj - vi + 19; if (dv >= 19) dv -= 19;
                int dh = hj - hi_lo + 31; if (dh >= 31) dh -= 31;
                float s = c[tn][e2] + pb[dv * 31 + dh];
                bool msk = (vmask && ((vi < 5) != (vj < 5))) ||
                           (hmask && ((hi_lo < 8) != (hj < 8)));
                s = msk ? NEG_INF : s;
                c[tn][e2] = s;
                mlo = fmaxf(mlo, s);
            }
            // row g+8
            {
                int dv = vj - vi + 19; if (dv >= 19) dv -= 19;
                int dh = hj - hi_hi + 31; if (dh >= 31) dh -= 31;
                float s = c[tn][2 + e2] + pb[dv * 31 + dh];
                bool msk = (vmask && ((vi < 5) != (vj < 5))) ||
                           (hmask && ((hi_hi < 8) != (hj < 8)));
                s = msk ? NEG_INF : s;
                c[tn][2 + e2] = s;
                mhi = fmaxf(mhi, s);
            }
        }
    }
    mlo = fmaxf(mlo, __shfl_xor_sync(0xffffffffu, mlo, 1));
    mlo = fmaxf(mlo, __shfl_xor_sync(0xffffffffu, mlo, 2));
    mhi = fmaxf(mhi, __shfl_xor_sync(0xffffffffu, mhi, 1));
    mhi = fmaxf(mhi, __shfl_xor_sync(0xffffffffu, mhi, 2));

    float slo = 0.0f, shi = 0.0f;
#pragma unroll
    for (int tn = 0; tn < 20; tn++) {
        float e0 = __expf(c[tn][0] - mlo);
        float e1 = __expf(c[tn][1] - mlo);
        float e2 = __expf(c[tn][2] - mhi);
        float e3 = __expf(c[tn][3] - mhi);
        c[tn][0] = e0; c[tn][1] = e1; c[tn][2] = e2; c[tn][3] = e3;
        slo += e0 + e1;
        shi += e2 + e3;
    }
    slo += __shfl_xor_sync(0xffffffffu, slo, 1);
    slo += __shfl_xor_sync(0xffffffffu, slo, 2);
    shi += __shfl_xor_sync(0xffffffffu, shi, 1);
    shi += __shfl_xor_sync(0xffffffffu, shi, 2);
    const float invlo = 1.0f / slo;
    const float invhi = 1.0f / shi;

    // ---- O = P V : warp rows x 64 cols (8 n-tiles), K=160 (10 ksteps).
    // P A-fragments come directly from S accumulators (D-layout == A-layout).
    float o[8][4];
#pragma unroll
    for (int j = 0; j < 8; j++)
#pragma unroll
        for (int k = 0; k < 4; k++) o[j][k] = 0.0f;

#pragma unroll
    for (int ks = 0; ks < 10; ks++) {
        uint32_t a[4];
        {
            __half2 p0 = __floats2half2_rn(c[2 * ks][0],     c[2 * ks][1]);
            __half2 p1 = __floats2half2_rn(c[2 * ks][2],     c[2 * ks][3]);
            __half2 p2 = __floats2half2_rn(c[2 * ks + 1][0], c[2 * ks + 1][1]);
            __half2 p3 = __floats2half2_rn(c[2 * ks + 1][2], c[2 * ks + 1][3]);
            a[0] = *(uint32_t*)&p0;
            a[1] = *(uint32_t*)&p1;
            a[2] = *(uint32_t*)&p2;
            a[3] = *(uint32_t*)&p3;
        }
#pragma unroll
        for (int tp = 0; tp < 4; tp++) {
            uint32_t bf[4];
            int vrow = ks * 16 + (lane & 15);
            int vcol = tp * 16 + ((lane >> 4) & 1) * 8;
            ldsm_x4t(bf, vbase + (uint32_t)(vrow * AS_STR + vcol) * 2);
            mma_f16(o[2 * tp],     a, bf);
            mma_f16(o[2 * tp + 1], a, bf + 2);
        }
    }

    // ---- Epilogue: normalize rows, write fp32
    const int row_lo = warp * 16 + g;
    float* og = out + ((size_t)(b * NW_ + w) * P_) * E_ + h * D_;
#pragma unroll
    for (int tn = 0; tn < 8; tn++) {
        const int col = tn * 8 + t * 2;
        float2 o2;
        o2.x = o[tn][0] * invlo;
        o2.y = o[tn][1] * invlo;
        *(float2*)(og + (size_t)row_lo * E_ + col) = o2;
        float2 o3;
        o3.x = o[tn][2] * invhi;
        o3.y = o[tn][3] * invhi;
        *(float2*)(og + (size_t)(row_lo + 8) * E_ + col) = o3;
    }
}

// ---------------------------------------------------------------------------
extern "C" void kernel_launch(void* const* d_in, const int* in_sizes, int n_in,
                              void* d_out, int out_size)
{
    const float* patches  = (const float*)d_in[0];
    const float* wq       = (const float*)d_in[1];
    const float* bq       = (const float*)d_in[2];
    const float* wk       = (const float*)d_in[3];
    const float* bk       = (const float*)d_in[4];
    const float* wv       = (const float*)d_in[5];
    const float* bv       = (const float*)d_in[6];
    const float* pos_bias = (const float*)d_in[7];
    float* out            = (float*)d_out;

    prepass<<<(TOT4 + 255) / 256, 256>>>(patches, wq, wk, wv);

    dim3 g1(M_ / 128, E_ / 128, 3);   // (640, 4, 3)
    qkv_mma<<<g1, 256>>>(bq, bk, bv);

    cudaFuncSetAttribute(attn_mma,
                         cudaFuncAttributeMaxDynamicSharedMemorySize, ATT_SMEM_BYTES);
    dim3 g2(NW_, H_, B_);             // (64, 8, 8)
    attn_mma<<<g2, 320, ATT_SMEM_BYTES>>>(pos_bias, out);
}